// round 8
// baseline (speedup 1.0000x reference)
#include <cuda_runtime.h>

// Problem constants (fixed by setup_inputs): B=8, N=16384, K=64
#define BB    8
#define NN    16384
#define KK    64
#define MTOT  (BB * NN)            // 131072 samples per channel
#define NROWS (BB * KK)            // 512 (b,k) rows
#define NHALF (NROWS * 2)          // 1024 half-row work units
// inv = -1/(2*sigma^2) = -12.5 ;  C = inv * log2(e)
#define CLOG2 (-18.033688011112043f)

#define GRID  444                  // 3 CTAs per SM on 148 SMs, all co-resident
#define TPB   256
#define NCHUNK (MTOT / TPB)        // 512 point-chunks of 256

// Scratch (no cudaMalloc allowed)
__device__ double g_sum[KK];
__device__ double g_ssum[KK];
__device__ unsigned g_work1;
__device__ unsigned g_work2;
__device__ unsigned g_arrive;              // grid barrier, monotonic across replays
__device__ volatile unsigned g_release;

typedef unsigned long long u64;

__device__ __forceinline__ float ex2f(float x) {
    float r;
    asm("ex2.approx.ftz.f32 %0, %1;" : "=f"(r) : "f"(x));
    return r;
}
__device__ __forceinline__ u64 pk2(float lo, float hi) {
    u64 r;
    asm("mov.b64 %0, {%1, %2};" : "=l"(r) : "f"(lo), "f"(hi));
    return r;
}
__device__ __forceinline__ void upk2(u64 v, float& a, float& b) {
    asm("mov.b64 {%0, %1}, %2;" : "=f"(a), "=f"(b) : "l"(v));
}
__device__ __forceinline__ u64 fma2(u64 a, u64 b, u64 c) {
    u64 d;
    asm("fma.rn.f32x2 %0, %1, %2, %3;" : "=l"(d) : "l"(a), "l"(b), "l"(c));
    return d;
}
__device__ __forceinline__ u64 mul2(u64 a, u64 b) {
    u64 d;
    asm("mul.rn.f32x2 %0, %1, %2;" : "=l"(d) : "l"(a), "l"(b));
    return d;
}

// Software grid barrier. Monotonic epoch counters -> safe across graph replays.
__device__ __forceinline__ void gsync() {
    __syncthreads();
    if (threadIdx.x == 0) {
        __threadfence();
        unsigned t = atomicAdd(&g_arrive, 1u);
        unsigned ep = t / GRID + 1u;
        if (t % GRID == GRID - 1u) {
            g_release = ep;
        } else {
            while (g_release < ep) { __nanosleep(64); }
        }
        __threadfence();
    }
    __syncthreads();
}

__global__ void __launch_bounds__(TPB, 3) fkc_fused(
    const float* __restrict__ normals,
    const void*  __restrict__ nidx,
    const float* __restrict__ wa,
    const float* __restrict__ wb,
    const float* __restrict__ gamma,
    const float* __restrict__ beta,
    float* __restrict__ out)
{
    __shared__ float4 sWtmp[KK * 4];   // (wx*s, wy*s, wz*s, we) per (k, m)
    __shared__ float4 sW2[KK * 4];     // packed-pair layout (A, B, C, D per k)
    __shared__ int sIdx32;
    __shared__ unsigned sChunk;
    __shared__ float sh_s[8], sh_ss[8];

    int tid = threadIdx.x;

    // Kernel-direction precompute (256 == KK*4 entries)
    {
        float a = wa[tid], b = wb[tid];
        float sa, ca, sb, cb;
        sincosf(a, &sa, &ca);
        sincosf(b, &sb, &cb);
        float wx = sa * cb, wy = sa * sb, wz = ca;
        float W2 = wx * wx + wy * wy + wz * wz;
        const float s = -2.0f * CLOG2;
        sWtmp[tid] = make_float4(wx * s, wy * s, wz * s, exp2f(CLOG2 * W2) * (1.0f / 16.0f));
    }
    if (tid == 0) {
        // Probe int32 (JAX default) vs int64 neighbor_idx
        int is32 = 0;
        const long long* p = (const long long*)nidx;
        for (int j = 0; j < 8; j++) {
            long long v = p[j];
            if (v < 0 || v >= NN) is32 = 1;
        }
        sIdx32 = is32;
    }
    if (blockIdx.x == 0 && tid < KK) { g_sum[tid] = 0.0; g_ssum[tid] = 0.0; }
    __syncthreads();

    // Repack per-k into m-pair layout for f32x2 math:
    //   A = (wx0, wx1, wy0, wy1)   B = (wz0, wz1, wx2, wx3)
    //   C = (wy2, wy3, wz2, wz3)   D = (we0, we1, we2, we3)
    {
        int k = tid >> 2, j = tid & 3;
        float4 W0 = sWtmp[4 * k + 0], W1 = sWtmp[4 * k + 1];
        float4 W2_ = sWtmp[4 * k + 2], W3 = sWtmp[4 * k + 3];
        float4 v;
        if (j == 0)      v = make_float4(W0.x, W1.x, W0.y, W1.y);
        else if (j == 1) v = make_float4(W0.z, W1.z, W2_.x, W3.x);
        else if (j == 2) v = make_float4(W2_.y, W3.y, W2_.z, W3.z);
        else             v = make_float4(W0.w, W1.w, W2_.w, W3.w);
        sW2[4 * k + j] = v;
    }
    __syncthreads();
    const int idx32 = sIdx32;

    // ---------------- Phase 1: compute feat (work-stealing) ----------------
    for (;;) {
        if (tid == 0) sChunk = atomicAdd(&g_work1, 1u);
        __syncthreads();
        unsigned c = sChunk;
        __syncthreads();
        if (c >= NCHUNK) break;

        int pid = (int)c * TPB + tid;
        int b = pid >> 14;            // / NN
        int n = pid & (NN - 1);
        const float* nb = normals + (size_t)b * (3 * NN);

        int jj[4];
        jj[0] = n;
        if (idx32) {
            const int* ip = (const int*)nidx + ((size_t)b * NN + n) * 3;
            jj[1] = ip[0]; jj[2] = ip[1]; jj[3] = ip[2];
        } else {
            const long long* ip = (const long long*)nidx + ((size_t)b * NN + n) * 3;
            jj[1] = (int)ip[0]; jj[2] = (int)ip[1]; jj[3] = (int)ip[2];
        }

        // Broadcast-packed face-point coords and E factor
        u64 ffx[4], ffy[4], ffz[4], EE[4];
#pragma unroll
        for (int p = 0; p < 4; p++) {
            float x = __ldg(nb + jj[p]);
            float y = __ldg(nb + NN + jj[p]);
            float z = __ldg(nb + 2 * NN + jj[p]);
            float E = ex2f(CLOG2 * (x * x + y * y + z * z));
            ffx[p] = pk2(x, x);
            ffy[p] = pk2(y, y);
            ffz[p] = pk2(z, z);
            EE[p] = pk2(E, E);
        }

        float* op = out + (size_t)b * KK * NN + n;
#pragma unroll 2
        for (int k = 0; k < KK; k++) {
            float4 A = sW2[4 * k + 0];
            float4 B = sW2[4 * k + 1];
            float4 C = sW2[4 * k + 2];
            float4 D = sW2[4 * k + 3];
            u64 wx01 = pk2(A.x, A.y), wy01 = pk2(A.z, A.w), wz01 = pk2(B.x, B.y);
            u64 wx23 = pk2(B.z, B.w), wy23 = pk2(C.x, C.y), wz23 = pk2(C.z, C.w);
            u64 acc01 = 0ull, acc23 = 0ull;
#pragma unroll
            for (int p = 0; p < 4; p++) {
                u64 d01 = fma2(ffx[p], wx01, fma2(ffy[p], wy01, mul2(ffz[p], wz01)));
                u64 d23 = fma2(ffx[p], wx23, fma2(ffy[p], wy23, mul2(ffz[p], wz23)));
                float e0, e1, e2, e3;
                upk2(d01, e0, e1);
                upk2(d23, e2, e3);
                acc01 = fma2(EE[p], pk2(ex2f(e0), ex2f(e1)), acc01);
                acc23 = fma2(EE[p], pk2(ex2f(e2), ex2f(e3)), acc23);
            }
            float a0, a1, a2, a3;
            upk2(acc01, a0, a1);
            upk2(acc23, a2, a3);
            op[(size_t)k * NN] = fmaf(a0, D.x, fmaf(a1, D.y, fmaf(a2, D.z, a3 * D.w)));
        }
    }

    gsync();   // all feat written, stats zeroed, g_work1 grabs done
    if (blockIdx.x == 0 && tid == 0) g_work1 = 0;   // reset for next replay

    // -------- Phase 2: per-(b,k) half-row sum / sumsq (L2-resident) --------
    for (;;) {
        if (tid == 0) sChunk = atomicAdd(&g_work2, 1u);
        __syncthreads();
        unsigned h = sChunk;
        __syncthreads();
        if (h >= NHALF) break;

        int r = (int)h >> 1;
        int k = r & (KK - 1);
        const float4* p4 = (const float4*)(out + (size_t)r * NN + (h & 1) * (NN / 2));
        float s = 0.f, ss = 0.f;
#pragma unroll
        for (int i = 0; i < NN / 8 / TPB; i++) {   // 8 iterations
            float4 v = p4[i * TPB + tid];
            s += (v.x + v.y) + (v.z + v.w);
            ss = fmaf(v.x, v.x, fmaf(v.y, v.y, fmaf(v.z, v.z, fmaf(v.w, v.w, ss))));
        }
#pragma unroll
        for (int o = 16; o; o >>= 1) {
            s  += __shfl_xor_sync(0xFFFFFFFFu, s, o);
            ss += __shfl_xor_sync(0xFFFFFFFFu, ss, o);
        }
        int w = tid >> 5, l = tid & 31;
        if (l == 0) { sh_s[w] = s; sh_ss[w] = ss; }
        __syncthreads();
        if (tid == 0) {
            float ts = 0.f, tss = 0.f;
#pragma unroll
            for (int i = 0; i < 8; i++) { ts += sh_s[i]; tss += sh_ss[i]; }
            atomicAdd(&g_sum[k],  (double)ts);
            atomicAdd(&g_ssum[k], (double)tss);
        }
        __syncthreads();
    }

    gsync();   // all stats accumulated
    if (blockIdx.x == 0 && tid == 0) g_work2 = 0;   // reset for next replay

    // ---------------- Phase 3: BN + ReLU in place (L2-resident) ------------
    for (int h = blockIdx.x; h < NHALF; h += GRID) {
        int r = h >> 1;
        int k = r & (KK - 1);
        double mean = g_sum[k] * (1.0 / MTOT);
        double var  = g_ssum[k] * (1.0 / MTOT) - mean * mean;
        float sc = __ldg(gamma + k) * rsqrtf((float)var + 1e-5f);
        float sh = __ldg(beta + k) - (float)mean * sc;
        float4* p4 = (float4*)(out + (size_t)r * NN + (h & 1) * (NN / 2));
#pragma unroll
        for (int i = 0; i < NN / 8 / TPB; i++) {   // 8 iterations
            float4 v = p4[i * TPB + tid];
            v.x = fmaxf(fmaf(v.x, sc, sh), 0.f);
            v.y = fmaxf(fmaf(v.y, sc, sh), 0.f);
            v.z = fmaxf(fmaf(v.z, sc, sh), 0.f);
            v.w = fmaxf(fmaf(v.w, sc, sh), 0.f);
            p4[i * TPB + tid] = v;
        }
    }
}

extern "C" void kernel_launch(void* const* d_in, const int* in_sizes, int n_in,
                              void* d_out, int out_size) {
    const float* normals = (const float*)d_in[0];
    const void*  nidx    = d_in[1];
    const float* wa      = (const float*)d_in[2];
    const float* wb      = (const float*)d_in[3];
    const float* gamma   = (const float*)d_in[4];
    const float* beta    = (const float*)d_in[5];
    float* out = (float*)d_out;

    fkc_fused<<<GRID, TPB>>>(normals, nidx, wa, wb, gamma, beta, out);
}

// round 9
// speedup vs baseline: 1.0110x; 1.0110x over previous
#include <cuda_runtime.h>

// Problem constants (fixed by setup_inputs): B=8, N=16384, K=64
#define BB    8
#define NN    16384
#define KK    64
#define MTOT  (BB * NN)            // 131072 samples per channel
#define NROWS (BB * KK)            // 512 (b,k) rows
#define NHALF (NROWS * 2)          // 1024 half-row work units
// inv = -1/(2*sigma^2) = -12.5 ;  C = inv * log2(e)
#define CLOG2 (-18.033688011112043f)

#define GRID  444                  // 3 CTAs per SM on 148 SMs, all co-resident
#define TPB   256
#define NCHUNK (MTOT / TPB)        // 512 point-chunks of 256

// Scratch (no cudaMalloc allowed)
__device__ double g_sum[KK];
__device__ double g_ssum[KK];
__device__ unsigned g_work1;
__device__ unsigned g_work2;
__device__ unsigned g_arrive;              // grid barrier, monotonic across replays
__device__ volatile unsigned g_release;

typedef unsigned long long u64;

__device__ __forceinline__ float ex2f(float x) {
    float r;
    asm("ex2.approx.ftz.f32 %0, %1;" : "=f"(r) : "f"(x));
    return r;
}
__device__ __forceinline__ u64 pk2(float lo, float hi) {
    u64 r;
    asm("mov.b64 %0, {%1, %2};" : "=l"(r) : "f"(lo), "f"(hi));
    return r;
}
__device__ __forceinline__ void upk2(u64 v, float& a, float& b) {
    asm("mov.b64 {%0, %1}, %2;" : "=f"(a), "=f"(b) : "l"(v));
}
__device__ __forceinline__ u64 fma2(u64 a, u64 b, u64 c) {
    u64 d;
    asm("fma.rn.f32x2 %0, %1, %2, %3;" : "=l"(d) : "l"(a), "l"(b), "l"(c));
    return d;
}
__device__ __forceinline__ u64 mul2(u64 a, u64 b) {
    u64 d;
    asm("mul.rn.f32x2 %0, %1, %2;" : "=l"(d) : "l"(a), "l"(b));
    return d;
}

// Software grid barrier. Monotonic epoch counters -> safe across graph replays.
__device__ __forceinline__ void gsync() {
    __syncthreads();
    if (threadIdx.x == 0) {
        __threadfence();
        unsigned t = atomicAdd(&g_arrive, 1u);
        unsigned ep = t / GRID + 1u;
        if (t % GRID == GRID - 1u) {
            g_release = ep;
        } else {
            while (g_release < ep) { __nanosleep(64); }
        }
        __threadfence();
    }
    __syncthreads();
}

__global__ void __launch_bounds__(TPB, 3) fkc_fused(
    const float* __restrict__ normals,
    const void*  __restrict__ nidx,
    const float* __restrict__ wa,
    const float* __restrict__ wb,
    const float* __restrict__ gamma,
    const float* __restrict__ beta,
    float* __restrict__ out)
{
    __shared__ float4 sWtmp[KK * 4];   // (wx*s, wy*s, wz*s, we) per (k, m)
    __shared__ float4 sW2[KK * 4];     // packed-pair layout (A, B, C, D per k)
    __shared__ int sIdx32;
    __shared__ unsigned sChunk;
    __shared__ float sh_s[8], sh_ss[8];

    int tid = threadIdx.x;

    // Kernel-direction precompute (256 == KK*4 entries)
    {
        float a = wa[tid], b = wb[tid];
        float sa, ca, sb, cb;
        sincosf(a, &sa, &ca);
        sincosf(b, &sb, &cb);
        float wx = sa * cb, wy = sa * sb, wz = ca;
        float W2 = wx * wx + wy * wy + wz * wz;
        const float s = -2.0f * CLOG2;
        sWtmp[tid] = make_float4(wx * s, wy * s, wz * s, exp2f(CLOG2 * W2) * (1.0f / 16.0f));
    }
    if (tid == 0) {
        // Probe int32 (JAX default) vs int64 neighbor_idx
        int is32 = 0;
        const long long* p = (const long long*)nidx;
        for (int j = 0; j < 8; j++) {
            long long v = p[j];
            if (v < 0 || v >= NN) is32 = 1;
        }
        sIdx32 = is32;
    }
    if (blockIdx.x == 0 && tid < KK) { g_sum[tid] = 0.0; g_ssum[tid] = 0.0; }
    __syncthreads();

    // Repack per-k into m-pair layout for f32x2 math:
    //   A = (wx0, wx1, wy0, wy1)   B = (wz0, wz1, wx2, wx3)
    //   C = (wy2, wy3, wz2, wz3)   D = (we0, we1, we2, we3)
    {
        int k = tid >> 2, j = tid & 3;
        float4 W0 = sWtmp[4 * k + 0], W1 = sWtmp[4 * k + 1];
        float4 W2_ = sWtmp[4 * k + 2], W3 = sWtmp[4 * k + 3];
        float4 v;
        if (j == 0)      v = make_float4(W0.x, W1.x, W0.y, W1.y);
        else if (j == 1) v = make_float4(W0.z, W1.z, W2_.x, W3.x);
        else if (j == 2) v = make_float4(W2_.y, W3.y, W2_.z, W3.z);
        else             v = make_float4(W0.w, W1.w, W2_.w, W3.w);
        sW2[4 * k + j] = v;
    }
    __syncthreads();
    const int idx32 = sIdx32;

    // ---------------- Phase 1: compute feat (work-stealing) ----------------
    for (;;) {
        if (tid == 0) sChunk = atomicAdd(&g_work1, 1u);
        __syncthreads();
        unsigned c = sChunk;
        __syncthreads();
        if (c >= NCHUNK) break;

        int pid = (int)c * TPB + tid;
        int b = pid >> 14;            // / NN
        int n = pid & (NN - 1);
        const float* nb = normals + (size_t)b * (3 * NN);

        int jj[4];
        jj[0] = n;
        if (idx32) {
            const int* ip = (const int*)nidx + ((size_t)b * NN + n) * 3;
            jj[1] = ip[0]; jj[2] = ip[1]; jj[3] = ip[2];
        } else {
            const long long* ip = (const long long*)nidx + ((size_t)b * NN + n) * 3;
            jj[1] = (int)ip[0]; jj[2] = (int)ip[1]; jj[3] = (int)ip[2];
        }

        // Broadcast-packed face-point coords and E factor
        u64 ffx[4], ffy[4], ffz[4], EE[4];
#pragma unroll
        for (int p = 0; p < 4; p++) {
            float x = __ldg(nb + jj[p]);
            float y = __ldg(nb + NN + jj[p]);
            float z = __ldg(nb + 2 * NN + jj[p]);
            float E = ex2f(CLOG2 * (x * x + y * y + z * z));
            ffx[p] = pk2(x, x);
            ffy[p] = pk2(y, y);
            ffz[p] = pk2(z, z);
            EE[p] = pk2(E, E);
        }

        float* op = out + (size_t)b * KK * NN + n;
#pragma unroll 2
        for (int k = 0; k < KK; k++) {
            float4 A = sW2[4 * k + 0];
            float4 B = sW2[4 * k + 1];
            float4 C = sW2[4 * k + 2];
            float4 D = sW2[4 * k + 3];
            u64 wx01 = pk2(A.x, A.y), wy01 = pk2(A.z, A.w), wz01 = pk2(B.x, B.y);
            u64 wx23 = pk2(B.z, B.w), wy23 = pk2(C.x, C.y), wz23 = pk2(C.z, C.w);
            u64 acc01 = 0ull, acc23 = 0ull;
#pragma unroll
            for (int p = 0; p < 4; p++) {
                u64 d01 = fma2(ffx[p], wx01, fma2(ffy[p], wy01, mul2(ffz[p], wz01)));
                u64 d23 = fma2(ffx[p], wx23, fma2(ffy[p], wy23, mul2(ffz[p], wz23)));
                float e0, e1, e2, e3;
                upk2(d01, e0, e1);
                upk2(d23, e2, e3);
                acc01 = fma2(EE[p], pk2(ex2f(e0), ex2f(e1)), acc01);
                acc23 = fma2(EE[p], pk2(ex2f(e2), ex2f(e3)), acc23);
            }
            float a0, a1, a2, a3;
            upk2(acc01, a0, a1);
            upk2(acc23, a2, a3);
            op[(size_t)k * NN] = fmaf(a0, D.x, fmaf(a1, D.y, fmaf(a2, D.z, a3 * D.w)));
        }
    }

    gsync();   // all feat written, stats zeroed, g_work1 grabs done
    if (blockIdx.x == 0 && tid == 0) g_work1 = 0;   // reset for next replay

    // -------- Phase 2: per-(b,k) half-row sum / sumsq (L2-resident) --------
    for (;;) {
        if (tid == 0) sChunk = atomicAdd(&g_work2, 1u);
        __syncthreads();
        unsigned h = sChunk;
        __syncthreads();
        if (h >= NHALF) break;

        int r = (int)h >> 1;
        int k = r & (KK - 1);
        const float4* p4 = (const float4*)(out + (size_t)r * NN + (h & 1) * (NN / 2));
        float s = 0.f, ss = 0.f;
#pragma unroll
        for (int i = 0; i < NN / 8 / TPB; i++) {   // 8 iterations
            float4 v = p4[i * TPB + tid];
            s += (v.x + v.y) + (v.z + v.w);
            ss = fmaf(v.x, v.x, fmaf(v.y, v.y, fmaf(v.z, v.z, fmaf(v.w, v.w, ss))));
        }
#pragma unroll
        for (int o = 16; o; o >>= 1) {
            s  += __shfl_xor_sync(0xFFFFFFFFu, s, o);
            ss += __shfl_xor_sync(0xFFFFFFFFu, ss, o);
        }
        int w = tid >> 5, l = tid & 31;
        if (l == 0) { sh_s[w] = s; sh_ss[w] = ss; }
        __syncthreads();
        if (tid == 0) {
            float ts = 0.f, tss = 0.f;
#pragma unroll
            for (int i = 0; i < 8; i++) { ts += sh_s[i]; tss += sh_ss[i]; }
            atomicAdd(&g_sum[k],  (double)ts);
            atomicAdd(&g_ssum[k], (double)tss);
        }
        __syncthreads();
    }

    gsync();   // all stats accumulated
    if (blockIdx.x == 0 && tid == 0) g_work2 = 0;   // reset for next replay

    // ---------------- Phase 3: BN + ReLU in place (L2-resident) ------------
    for (int h = blockIdx.x; h < NHALF; h += GRID) {
        int r = h >> 1;
        int k = r & (KK - 1);
        double mean = g_sum[k] * (1.0 / MTOT);
        double var  = g_ssum[k] * (1.0 / MTOT) - mean * mean;
        float sc = __ldg(gamma + k) * rsqrtf((float)var + 1e-5f);
        float sh = __ldg(beta + k) - (float)mean * sc;
        float4* p4 = (float4*)(out + (size_t)r * NN + (h & 1) * (NN / 2));
#pragma unroll
        for (int i = 0; i < NN / 8 / TPB; i++) {   // 8 iterations
            float4 v = p4[i * TPB + tid];
            v.x = fmaxf(fmaf(v.x, sc, sh), 0.f);
            v.y = fmaxf(fmaf(v.y, sc, sh), 0.f);
            v.z = fmaxf(fmaf(v.z, sc, sh), 0.f);
            v.w = fmaxf(fmaf(v.w, sc, sh), 0.f);
            p4[i * TPB + tid] = v;
        }
    }
}

extern "C" void kernel_launch(void* const* d_in, const int* in_sizes, int n_in,
                              void* d_out, int out_size) {
    const float* normals = (const float*)d_in[0];
    const void*  nidx    = d_in[1];
    const float* wa      = (const float*)d_in[2];
    const float* wb      = (const float*)d_in[3];
    const float* gamma   = (const float*)d_in[4];
    const float* beta    = (const float*)d_in[5];
    float* out = (float*)d_out;

    fkc_fused<<<GRID, TPB>>>(normals, nidx, wa, wb, gamma, beta, out);
}